// round 9
// baseline (speedup 1.0000x reference)
#include <cuda_runtime.h>
#include <cuda_bf16.h>
#include <math.h>

#define Nn   16000
#define Ee   48000
#define Ff   32000
#define Dd   64
#define Bb   32
#define Gg   32
#define HIDN 256
#define NCc  10

#define DSLICE 4
#define NSLICE (Dd / DSLICE)          // 16
#define CHUNKS 40
#define M_TOTAL (Nn + Ee + Ff)        // 96000
#define ITEMS_PER_CHUNK ((M_TOTAL + CHUNKS - 1) / CHUNKS)  // 2400

#define C_HALF 3.2258064516f          // 0.5 * SCALE * (2/31)
#define INV_DL 15.5f

#define SIG_SZ (Gg * Bb * DSLICE)              // 4096
#define STEP_SZ (Gg * (Bb + 1) * DSLICE)       // 4224
#define PART_SZ (SIG_SZ + STEP_SZ)             // 8320

#define KC 8
#define JG 32
#define FPAD 4
#define FSTRIDE (256 + FPAD)

// scratch (device globals: no allocations allowed)
__device__ float d_nh[Nn * Dd];                        // 4 MB node heights
__device__ float d_t[NSLICE * M_TOTAL * DSLICE];       // 24.6 MB staged t (plane-major)
__device__ unsigned char d_meta[M_TOTAL];              // g | (sign<<7)
__device__ float d_part[CHUNKS * NSLICE * PART_SZ];    // 21.3 MB per-block partials
__device__ float d_sig[Gg * Bb * Dd];
__device__ float d_step[Gg * (Bb + 1) * Dd];
__device__ float d_h[Gg * HIDN];

// nh compute + d_h seed
__global__ void init_kernel(const float* __restrict__ x, const float* __restrict__ nw,
                            const float* __restrict__ v, const float* __restrict__ b1) {
    int i = blockIdx.x * blockDim.x + threadIdx.x;
    if (i < Gg * HIDN) d_h[i] = b1[i & (HIDN - 1)];
    if (i >= Nn * (Dd / 4)) return;
    int n = i >> 4, q = i & 15;
    float w = nw[n];
    float x0 = x[n * 3 + 0] * w, x1 = x[n * 3 + 1] * w, x2 = x[n * 3 + 2] * w;
    float4 v0 = ((const float4*)(v))[q];
    float4 v1 = ((const float4*)(v + Dd))[q];
    float4 v2 = ((const float4*)(v + 2 * Dd))[q];
    float4 r;
    r.x = x0 * v0.x + x1 * v1.x + x2 * v2.x;
    r.y = x0 * v0.y + x1 * v1.y + x2 * v2.y;
    r.z = x0 * v0.z + x1 * v1.z + x2 * v2.z;
    r.w = x0 * v0.w + x1 * v1.w + x2 * v2.w;
    ((float4*)d_nh)[i] = r;
}

// stage: per item, compute t for all 64 dirs + meta byte
__global__ void __launch_bounds__(128) stage_kernel(
    const float* __restrict__ ew, const float* __restrict__ fw,
    const int* __restrict__ eidx, const int* __restrict__ fidx,
    const int* __restrict__ batch)
{
    int item = blockIdx.x * 128 + threadIdx.x;
    if (item >= M_TOTAL) return;

    const float4* nhv = (const float4*)d_nh;
    float4* tv = (float4*)d_t;

    if (item < Nn) {
        d_meta[item] = (unsigned char)batch[item];
        #pragma unroll 4
        for (int q = 0; q < 16; ++q) {
            float4 h = nhv[item * 16 + q];
            float4 t;
            t.x = fmaf(h.x, INV_DL, INV_DL);
            t.y = fmaf(h.y, INV_DL, INV_DL);
            t.z = fmaf(h.z, INV_DL, INV_DL);
            t.w = fmaf(h.w, INV_DL, INV_DL);
            tv[q * M_TOTAL + item] = t;
        }
    } else if (item < Nn + Ee) {
        int e = item - Nn;
        int a = eidx[e], b = eidx[Ee + e];
        float w = ew[e];
        d_meta[item] = (unsigned char)(batch[a] | 128);   // negative sign
        #pragma unroll 4
        for (int q = 0; q < 16; ++q) {
            float4 ha = nhv[a * 16 + q];
            float4 hb = nhv[b * 16 + q];
            float4 t;
            t.x = fmaf(fmaxf(ha.x, hb.x) * w, INV_DL, INV_DL);
            t.y = fmaf(fmaxf(ha.y, hb.y) * w, INV_DL, INV_DL);
            t.z = fmaf(fmaxf(ha.z, hb.z) * w, INV_DL, INV_DL);
            t.w = fmaf(fmaxf(ha.w, hb.w) * w, INV_DL, INV_DL);
            tv[q * M_TOTAL + item] = t;
        }
    } else {
        int f = item - Nn - Ee;
        int a = fidx[f], b = fidx[Ff + f], c = fidx[2 * Ff + f];
        float w = fw[f];
        d_meta[item] = (unsigned char)batch[a];
        #pragma unroll 4
        for (int q = 0; q < 16; ++q) {
            float4 ha = nhv[a * 16 + q];
            float4 hb = nhv[b * 16 + q];
            float4 hc = nhv[c * 16 + q];
            float4 t;
            t.x = fmaf(fmaxf(fmaxf(ha.x, hb.x), hc.x) * w, INV_DL, INV_DL);
            t.y = fmaf(fmaxf(fmaxf(ha.y, hb.y), hc.y) * w, INV_DL, INV_DL);
            t.z = fmaf(fmaxf(fmaxf(ha.z, hb.z), hc.z) * w, INV_DL, INV_DL);
            t.w = fmaf(fmaxf(fmaxf(ha.w, hb.w), hc.w) * w, INV_DL, INV_DL);
            tv[q * M_TOTAL + item] = t;
        }
    }
}

__device__ __forceinline__ float fast_tanh(float u) {
    float r;
    asm("tanh.approx.f32 %0, %1;" : "=f"(r) : "f"(u));
    return r;
}

// binning: lean loop, shared atomics, private-region flush (no global atomics)
__global__ void __launch_bounds__(256) ecc_kernel()
{
    __shared__ float s_all[PART_SZ];       // 33.3 KB: [0,4096) sig, [4096,8320) step
    float* s_sig = s_all;
    float* s_step = s_all + SIG_SZ;
    const int tid = threadIdx.x;
    for (int i = tid; i < PART_SZ; i += 256) s_all[i] = 0.f;
    __syncthreads();

    const int slice = blockIdx.y;
    const int dloc  = tid & (DSLICE - 1);
    const int itemoff = tid >> 2;                      // 0..63
    const int base = blockIdx.x * ITEMS_PER_CHUNK;
    const int iend = min(M_TOTAL, base + ITEMS_PER_CHUNK);
    const float* tplane = &d_t[slice * M_TOTAL * DSLICE];

    for (int id = base + itemoff; id < iend; id += 64) {
        float t = tplane[id * DSLICE + dloc];          // 128B coalesced per warp
        unsigned m = d_meta[id];                       // 8B per warp, cached
        int g = (int)(m & 31u);
        float sign = (m & 128u) ? -1.f : 1.f;

        float rff = floorf(t + 0.5f);
        int rr = (int)rff;
        int b_end = min(max(rr + 2, 0), Bb);

        float shalf = 0.5f * sign;
        float u = (rff - 1.0f - t) * C_HALF;
        float* sb = &s_sig[(g * Bb) * DSLICE + dloc];
        #pragma unroll
        for (int j = 0; j < 3; ++j) {
            int b = rr - 1 + j;
            float val = fmaf(shalf, fast_tanh(u), shalf);
            if ((unsigned)b < (unsigned)Bb) {
                atomicAdd(sb + b * DSLICE, val);
            }
            u += C_HALF;
        }
        atomicAdd(&s_step[(g * (Bb + 1) + b_end) * DSLICE + dloc], sign);
    }
    __syncthreads();

    // flush to this block's private region: plain coalesced stores
    float4* part = (float4*)&d_part[(size_t)(blockIdx.x * NSLICE + slice) * PART_SZ];
    const float4* src = (const float4*)s_all;
    for (int i = tid; i < PART_SZ / 4; i += 256) part[i] = src[i];
}

// sum the CHUNKS partials per slice; scatter into d_sig / d_step [g][b][d] layout
__global__ void reduce_kernel() {
    int j = blockIdx.x * 256 + threadIdx.x;
    int sl = blockIdx.y;
    if (j >= PART_SZ) return;
    float sum = 0.f;
    #pragma unroll 8
    for (int c = 0; c < CHUNKS; ++c)
        sum += d_part[(size_t)(c * NSLICE + sl) * PART_SZ + j];
    if (j < SIG_SZ) {
        int row = j >> 2, dl = j & 3;                  // row = g*32+b
        d_sig[row * Dd + sl * DSLICE + dl] = sum;
    } else {
        int j2 = j - SIG_SZ;
        int row = j2 >> 2, dl = j2 & 3;                // row = g*33+b
        d_step[row * Dd + sl * DSLICE + dl] = sum;
    }
}

// prefix over bumps: flat[g][b][d] = sig + running step
__global__ void combine_kernel(float* __restrict__ flat) {
    int g = blockIdx.x;
    int d = threadIdx.x;                // 64 threads
    float run = 0.f;
    const float* stp = &d_step[g * (Bb + 1) * Dd + d];
    const float* sgp = &d_sig[g * Bb * Dd + d];
    float* fp = &flat[g * Bb * Dd + d];
    #pragma unroll 8
    for (int b = 0; b < Bb; ++b) {
        run += stp[b * Dd];
        fp[b * Dd] = sgp[b * Dd] + run;
    }
}

// first GEMM layer, split-K over bump chunks
__global__ void __launch_bounds__(256) mlp1_kernel(
    const float* __restrict__ W1, const float* __restrict__ flat)
{
    __shared__ float s_f[Gg * FSTRIDE];
    __shared__ float s_w[8 * 256];
    const int tid = threadIdx.x;
    const int kc = blockIdx.x;
    const int jg = blockIdx.y;
    const int bb0 = kc * 4;

    #pragma unroll
    for (int r = 0; r < 8; ++r) {
        int idx = tid + r * 256;
        int g = idx >> 6;
        int c4 = idx & 63;
        float4 val = *(const float4*)&flat[(size_t)(g * Bb + bb0) * Dd + c4 * 4];
        *(float4*)&s_f[g * FSTRIDE + c4 * 4] = val;
    }
    {
        const int koff = bb0 * Dd;
        #pragma unroll
        for (int r = 0; r < 2; ++r) {
            int idx = tid + r * 256;
            int row = idx >> 6, col = (idx & 63) << 2;
            ((float4*)s_w)[idx] = *(const float4*)&W1[(size_t)(jg * 8 + row) * (Bb * Dd) + koff + col];
        }
    }
    __syncthreads();

    const int j = tid >> 5;
    const int g = tid & 31;
    const float4* wrow = (const float4*)&s_w[j * 256];
    const float* frow = &s_f[g * FSTRIDE];
    float acc = 0.f;
    #pragma unroll 8
    for (int k4 = 0; k4 < 64; ++k4) {
        float4 w = wrow[k4];
        float4 f = *(const float4*)&frow[k4 * 4];
        acc = fmaf(w.x, f.x, acc);
        acc = fmaf(w.y, f.y, acc);
        acc = fmaf(w.z, f.z, acc);
        acc = fmaf(w.w, f.w, acc);
    }
    atomicAdd(&d_h[g * HIDN + jg * 8 + j], acc);
}

// relu + second layer: one warp per output class
__global__ void __launch_bounds__(320) mlp2_kernel(
    const float* __restrict__ W2, const float* __restrict__ b2,
    float* __restrict__ logits)
{
    const int g = blockIdx.x;
    const int w = threadIdx.x >> 5;
    const int lane = threadIdx.x & 31;
    float acc = 0.f;
    #pragma unroll
    for (int k8 = 0; k8 < HIDN / 32; ++k8) {
        int k = k8 * 32 + lane;
        float hv = fmaxf(d_h[g * HIDN + k], 0.f);
        acc = fmaf(hv, W2[w * HIDN + k], acc);
    }
    #pragma unroll
    for (int off = 16; off; off >>= 1)
        acc += __shfl_xor_sync(0xffffffffu, acc, off);
    if (lane == 0) logits[g * NCc + w] = b2[w] + acc;
}

extern "C" void kernel_launch(void* const* d_in, const int* in_sizes, int n_in,
                              void* d_out, int out_size) {
    const float* x   = (const float*)d_in[0];
    const float* nw  = (const float*)d_in[1];
    const float* ew  = (const float*)d_in[2];
    const float* fw  = (const float*)d_in[3];
    const float* v   = (const float*)d_in[4];
    const float* W1  = (const float*)d_in[5];
    const float* b1  = (const float*)d_in[6];
    const float* W2  = (const float*)d_in[7];
    const float* b2  = (const float*)d_in[8];
    const int* eidx  = (const int*)d_in[9];
    const int* fidx  = (const int*)d_in[10];
    const int* batch = (const int*)d_in[11];

    float* out = (float*)d_out;
    float* logits = out;                 // [32, 10]
    float* flat   = out + Gg * NCc;      // [32, 2048]

    init_kernel<<<(Nn * (Dd / 4) + 255) / 256, 256>>>(x, nw, v, b1);
    stage_kernel<<<(M_TOTAL + 127) / 128, 128>>>(ew, fw, eidx, fidx, batch);
    dim3 egrid(CHUNKS, NSLICE);
    ecc_kernel<<<egrid, 256>>>();
    dim3 rgrid((PART_SZ + 255) / 256, NSLICE);
    reduce_kernel<<<rgrid, 256>>>();
    combine_kernel<<<Gg, Dd>>>(flat);
    dim3 mgrid(KC, JG);
    mlp1_kernel<<<mgrid, 256>>>(W1, flat);
    mlp2_kernel<<<Gg, 320>>>(W2, b2, logits);
}